// round 12
// baseline (speedup 1.0000x reference)
#include <cuda_runtime.h>
#include <cuda_fp16.h>
#include <math.h>
#include <stdint.h>

// PointLoss_like_GPS — GB300 sm_103a, Round 12
// Dual-pipe brute force on the proven R11 skeleton:
//   refs[0:256)  -> fp16x2 engine (HSUB2/HADD2, fma pipe)
//   refs[256:512)-> int16x2 DPX engine (VABSDIFF2/VADDSS2/VMIN2, alu pipe)
// Saturating int adds make overflow harmless (clamps >> real dmin).

#define NPTS    4096
#define DIMS    3
#define THREADS 256
#define SPLITS  8
#define RSPLIT  (NPTS / SPLITS)      // 512 refs per block
#define HALFR   (RSPLIT / 2)         // 256 per engine
#define MAXQ    32768
#define FINB    8
#define ISCALE  2048.0f
#define IINV    (1.0f / 2048.0f)

__device__ float        g_dmin[MAXQ * SPLITS];
__device__ float        g_fpart[FINB];
__device__ unsigned int g_ticket1;
__device__ unsigned int g_ticket2;

__device__ __forceinline__ __half2 h2_of(unsigned int u)
{
    return *reinterpret_cast<const __half2*>(&u);
}

__global__ void __launch_bounds__(THREADS, 6)
gps_kernel(const float* __restrict__ a1,
           const float* __restrict__ a2,
           const float* __restrict__ alpha_p,
           const float* __restrict__ beta_p,
           float* __restrict__ out,
           int nq, int nblocks, float scale)
{
    __shared__ __align__(16) __half2      shX [HALFR / 2];  // 128 half2
    __shared__ __align__(16) __half2      shY [HALFR / 2];
    __shared__ __align__(16) __half2      shZ [HALFR / 2];
    __shared__ __align__(16) unsigned int shXi[HALFR / 2];  // 128 short2
    __shared__ __align__(16) unsigned int shYi[HALFR / 2];
    __shared__ __align__(16) unsigned int shZi[HALFR / 2];
    __shared__ float red[THREADS / 32];
    __shared__ unsigned int s_ticket;

    const int tid = threadIdx.x;
    const int bx  = blockIdx.x;

    const int sp   = bx & (SPLITS - 1);
    const int qc   = (bx >> 3) & 15;
    const int pair = bx >> 7;
    const int q    = (qc << 8) + tid;
    const int b    = pair >> 1;

    const float* base1 = a1 + (size_t)b * NPTS * DIMS;
    const float* base2 = a2 + (size_t)b * NPTS * DIMS;
    const float* samples = (pair & 1) ? base1 : base2;
    const float* refs    = ((pair & 1) ? base2 : base1) + (size_t)sp * RSPLIT * DIMS;

    const float qx = samples[q * 3 + 0];
    const float qy = samples[q * 3 + 1];
    const float qz = samples[q * 3 + 2];

    const __half2 qx2 = __floats2half2_rn(qx, qx);
    const __half2 qy2 = __floats2half2_rn(qy, qy);
    const __half2 qz2 = __floats2half2_rn(qz, qz);

    const int qxi = __float2int_rn(qx * ISCALE);
    const int qyi = __float2int_rn(qy * ISCALE);
    const int qzi = __float2int_rn(qz * ISCALE);
    const unsigned int qx2i = (unsigned int)((qxi & 0xFFFF) | (qxi << 16));
    const unsigned int qy2i = (unsigned int)((qyi & 0xFFFF) | (qyi << 16));
    const unsigned int qz2i = (unsigned int)((qzi & 0xFFFF) | (qzi << 16));

    // tile conversion: threads [0,128) build fp16 half; [128,256) build int16 half
    if (tid < HALFR / 2) {
        const float* p = refs + (size_t)tid * 6;           // pts 2t, 2t+1
        shX[tid] = __floats2half2_rn(p[0], p[3]);
        shY[tid] = __floats2half2_rn(p[1], p[4]);
        shZ[tid] = __floats2half2_rn(p[2], p[5]);
    } else {
        const int t2 = tid - HALFR / 2;
        const float* p = refs + (size_t)(HALFR + t2 * 2) * 3;
        const int x0 = __float2int_rn(p[0] * ISCALE);
        const int y0 = __float2int_rn(p[1] * ISCALE);
        const int z0 = __float2int_rn(p[2] * ISCALE);
        const int x1 = __float2int_rn(p[3] * ISCALE);
        const int y1 = __float2int_rn(p[4] * ISCALE);
        const int z1 = __float2int_rn(p[5] * ISCALE);
        shXi[t2] = (unsigned int)((x0 & 0xFFFF) | (x1 << 16));
        shYi[t2] = (unsigned int)((y0 & 0xFFFF) | (y1 << 16));
        shZi[t2] = (unsigned int)((z0 & 0xFFFF) | (z1 << 16));
    }
    __syncthreads();

    const __half2 HMAXV = __float2half2_rn(65504.0f);
    __half2 am0 = HMAXV, am1 = HMAXV;
    unsigned int im0 = 0x7FFF7FFFu, im1 = 0x7FFF7FFFu;

    const uint4* Xf = (const uint4*)shX;    // 32 groups x 8 pts
    const uint4* Yf = (const uint4*)shY;
    const uint4* Zf = (const uint4*)shZ;
    const uint4* Xi = (const uint4*)shXi;
    const uint4* Yi = (const uint4*)shYi;
    const uint4* Zi = (const uint4*)shZi;

    #pragma unroll 4
    for (int j = 0; j < HALFR / 8; j++) {
        const uint4 xf = Xf[j], yf = Yf[j], zf = Zf[j];
        const uint4 xi = Xi[j], yi = Yi[j], zi = Zi[j];

        // ---- fp16x2 engine (fma pipe): 8 points ----
        {
            const __half2 a0 = __habs2(__hsub2(qx2, h2_of(xf.x)));
            const __half2 b0 = __habs2(__hsub2(qy2, h2_of(yf.x)));
            const __half2 c0 = __habs2(__hsub2(qz2, h2_of(zf.x)));
            am0 = __hmin2(am0, __hadd2(__hadd2(a0, b0), c0));

            const __half2 a1v = __habs2(__hsub2(qx2, h2_of(xf.y)));
            const __half2 b1v = __habs2(__hsub2(qy2, h2_of(yf.y)));
            const __half2 c1v = __habs2(__hsub2(qz2, h2_of(zf.y)));
            am1 = __hmin2(am1, __hadd2(__hadd2(a1v, b1v), c1v));

            const __half2 a2v = __habs2(__hsub2(qx2, h2_of(xf.z)));
            const __half2 b2v = __habs2(__hsub2(qy2, h2_of(yf.z)));
            const __half2 c2v = __habs2(__hsub2(qz2, h2_of(zf.z)));
            am0 = __hmin2(am0, __hadd2(__hadd2(a2v, b2v), c2v));

            const __half2 a3v = __habs2(__hsub2(qx2, h2_of(xf.w)));
            const __half2 b3v = __habs2(__hsub2(qy2, h2_of(yf.w)));
            const __half2 c3v = __habs2(__hsub2(qz2, h2_of(zf.w)));
            am1 = __hmin2(am1, __hadd2(__hadd2(a3v, b3v), c3v));
        }

        // ---- int16x2 DPX engine (alu pipe): 8 points ----
        {
            const unsigned int dx0 = __vabsdiffs2(qx2i, xi.x);
            const unsigned int dy0 = __vabsdiffs2(qy2i, yi.x);
            const unsigned int dz0 = __vabsdiffs2(qz2i, zi.x);
            im0 = __vmins2(im0, __vaddss2(__vaddss2(dx0, dy0), dz0));

            const unsigned int dx1 = __vabsdiffs2(qx2i, xi.y);
            const unsigned int dy1 = __vabsdiffs2(qy2i, yi.y);
            const unsigned int dz1 = __vabsdiffs2(qz2i, zi.y);
            im1 = __vmins2(im1, __vaddss2(__vaddss2(dx1, dy1), dz1));

            const unsigned int dx2 = __vabsdiffs2(qx2i, xi.z);
            const unsigned int dy2 = __vabsdiffs2(qy2i, yi.z);
            const unsigned int dz2 = __vabsdiffs2(qz2i, zi.z);
            im0 = __vmins2(im0, __vaddss2(__vaddss2(dx2, dy2), dz2));

            const unsigned int dx3 = __vabsdiffs2(qx2i, xi.w);
            const unsigned int dy3 = __vabsdiffs2(qy2i, yi.w);
            const unsigned int dz3 = __vabsdiffs2(qz2i, zi.w);
            im1 = __vmins2(im1, __vaddss2(__vaddss2(dx3, dy3), dz3));
        }
    }

    // combine engines
    const __half2 am = __hmin2(am0, am1);
    float dmin = fminf(__low2float(am), __high2float(am));

    const unsigned int im = __vmins2(im0, im1);
    const int ilo = (int)(short)(im & 0xFFFF);
    const int ihi = (int)(short)(im >> 16);
    const float idmin = (float)min(ilo, ihi) * IINV;
    dmin = fminf(dmin, idmin);

    g_dmin[(size_t)(pair * NPTS + q) * SPLITS + sp] = dmin;

    // ---- ticketed tail: last FINB blocks finalize (proven structure) ----
    __syncthreads();
    if (tid == 0) {
        __threadfence();
        s_ticket = atomicAdd(&g_ticket1, 1u);
    }
    __syncthreads();
    const unsigned int t = s_ticket;
    if (t < (unsigned)(nblocks - FINB)) return;

    const int rank = (int)t - (nblocks - FINB);

    if (tid == 0) {
        while (*((volatile unsigned int*)&g_ticket1) < (unsigned)nblocks) { }
    }
    __syncthreads();
    __threadfence();

    const float alpha = *alpha_p;
    const float beta  = *beta_p;
    const float delta = __powf(alpha, -1.0f / beta);

    const int per_blk = nq / FINB;               // 4096 queries
    const int qbase   = rank * per_blk;
    const float4* dm4 = (const float4*)g_dmin;

    float acc = 0.0f;
    #pragma unroll 2
    for (int i = tid; i < per_blk; i += THREADS) {
        const float4 d0 = dm4[(size_t)(qbase + i) * 2 + 0];
        const float4 d1 = dm4[(size_t)(qbase + i) * 2 + 1];
        float dmn = fminf(fminf(fminf(d0.x, d0.y), fminf(d0.z, d0.w)),
                          fminf(fminf(d1.x, d1.y), fminf(d1.z, d1.w)));
        const float sv = alpha * __powf(dmn, beta) + delta;
        acc += -sv * __expf(-sv);
    }

    #pragma unroll
    for (int o = 16; o > 0; o >>= 1)
        acc += __shfl_down_sync(0xffffffffu, acc, o);
    if ((tid & 31) == 0) red[tid >> 5] = acc;
    __syncthreads();

    if (tid == 0) {
        float v = 0.0f;
        #pragma unroll
        for (int w = 0; w < THREADS / 32; w++) v += red[w];
        g_fpart[rank] = v;
        __threadfence();
        const unsigned int t2 = atomicAdd(&g_ticket2, 1u);
        if (t2 == FINB - 1) {
            float total = 0.0f;
            #pragma unroll
            for (int r = 0; r < FINB; r++)
                total += *((volatile float*)&g_fpart[r]);
            out[0] = total * scale;
            g_ticket1 = 0;
            g_ticket2 = 0;
        }
    }
}

extern "C" void kernel_launch(void* const* d_in, const int* in_sizes, int n_in,
                              void* d_out, int out_size)
{
    const float* a1    = (const float*)d_in[0];
    const float* a2    = (const float*)d_in[1];
    const float* alpha = (const float*)d_in[2];
    const float* beta  = (const float*)d_in[3];
    float* out = (float*)d_out;

    const int B  = in_sizes[0] / (NPTS * DIMS);
    const int nq = 2 * B * NPTS;
    const int nblocks = 2 * B * 16 * SPLITS;     // 1024 at B=4
    const float scale = 50.0f / (float)B;

    gps_kernel<<<nblocks, THREADS>>>(a1, a2, alpha, beta, out, nq, nblocks, scale);
}

// round 13
// speedup vs baseline: 1.8052x; 1.8052x over previous
#include <cuda_runtime.h>
#include <cuda_fp16.h>
#include <math.h>
#include <stdint.h>

// PointLoss_like_GPS — GB300 sm_103a, Round 13
// R11 fp16x2 engine (proven 31.2us) with SPLITS=4: 512 uniform blocks, all
// co-resident in ONE wave (512 <= 6*152) -> zero wave quantization.

#define NPTS    4096
#define DIMS    3
#define THREADS 256
#define SPLITS  4
#define RSPLIT  (NPTS / SPLITS)      // 1024 refs per block
#define MAXQ    32768                // 2B*N at B=4
#define FINB    8                    // finalizer blocks

__device__ float        g_dmin[MAXQ * SPLITS];  // layout [q][split]
__device__ float        g_fpart[FINB];
__device__ unsigned int g_ticket1;
__device__ unsigned int g_ticket2;

__device__ __forceinline__ __half2 h2_of(unsigned int u)
{
    return *reinterpret_cast<const __half2*>(&u);
}

__global__ void __launch_bounds__(THREADS, 6)
gps_kernel(const float* __restrict__ a1,
           const float* __restrict__ a2,
           const float* __restrict__ alpha_p,
           const float* __restrict__ beta_p,
           float* __restrict__ out,
           int nq, int nblocks, float scale)
{
    __shared__ __align__(16) __half2 shX[RSPLIT / 2];   // 1024 pts = 512 half2
    __shared__ __align__(16) __half2 shY[RSPLIT / 2];
    __shared__ __align__(16) __half2 shZ[RSPLIT / 2];
    __shared__ float red[THREADS / 32];
    __shared__ unsigned int s_ticket;

    const int tid = threadIdx.x;
    const int bx  = blockIdx.x;

    // bx = pair*(16*SPLITS) + qc*SPLITS + sp
    const int sp   = bx & (SPLITS - 1);
    const int qc   = (bx >> 2) & 15;
    const int pair = bx >> 6;
    const int q    = (qc << 8) + tid;
    const int b    = pair >> 1;

    const float* base1 = a1 + (size_t)b * NPTS * DIMS;
    const float* base2 = a2 + (size_t)b * NPTS * DIMS;
    const float* samples = (pair & 1) ? base1 : base2;
    const float* refs    = ((pair & 1) ? base2 : base1) + (size_t)sp * RSPLIT * DIMS;

    const float qx = samples[q * 3 + 0];
    const float qy = samples[q * 3 + 1];
    const float qz = samples[q * 3 + 2];

    const __half2 qx2 = __floats2half2_rn(qx, qx);
    const __half2 qy2 = __floats2half2_rn(qy, qy);
    const __half2 qz2 = __floats2half2_rn(qz, qz);

    // tile: each thread converts 4 ref points (AoS fp32 -> half2 SoA)
    #pragma unroll
    for (int k = 0; k < RSPLIT / 2 / THREADS; k++) {
        const int idx = tid + k * THREADS;          // half2 index
        const float* p = refs + (size_t)idx * 6;    // points 2*idx, 2*idx+1
        shX[idx] = __floats2half2_rn(p[0], p[3]);
        shY[idx] = __floats2half2_rn(p[1], p[4]);
        shZ[idx] = __floats2half2_rn(p[2], p[5]);
    }
    __syncthreads();

    const __half2 HMAXV = __float2half2_rn(65504.0f);
    __half2 am0 = HMAXV, am1 = HMAXV, am2 = HMAXV, am3 = HMAXV;

    const uint4* X = (const uint4*)shX;   // 128 uint4 = 512 half2 = 1024 pts
    const uint4* Y = (const uint4*)shY;
    const uint4* Z = (const uint4*)shZ;

    #pragma unroll 4
    for (int j = 0; j < RSPLIT / 8; j++) {
        const uint4 xv = X[j], yv = Y[j], zv = Z[j];

        const __half2 ax0 = __habs2(__hsub2(qx2, h2_of(xv.x)));
        const __half2 ay0 = __habs2(__hsub2(qy2, h2_of(yv.x)));
        const __half2 az0 = __habs2(__hsub2(qz2, h2_of(zv.x)));
        am0 = __hmin2(am0, __hadd2(__hadd2(ax0, ay0), az0));

        const __half2 ax1 = __habs2(__hsub2(qx2, h2_of(xv.y)));
        const __half2 ay1 = __habs2(__hsub2(qy2, h2_of(yv.y)));
        const __half2 az1 = __habs2(__hsub2(qz2, h2_of(zv.y)));
        am1 = __hmin2(am1, __hadd2(__hadd2(ax1, ay1), az1));

        const __half2 ax2 = __habs2(__hsub2(qx2, h2_of(xv.z)));
        const __half2 ay2 = __habs2(__hsub2(qy2, h2_of(yv.z)));
        const __half2 az2 = __habs2(__hsub2(qz2, h2_of(zv.z)));
        am2 = __hmin2(am2, __hadd2(__hadd2(ax2, ay2), az2));

        const __half2 ax3 = __habs2(__hsub2(qx2, h2_of(xv.w)));
        const __half2 ay3 = __habs2(__hsub2(qy2, h2_of(yv.w)));
        const __half2 az3 = __habs2(__hsub2(qz2, h2_of(zv.w)));
        am3 = __hmin2(am3, __hadd2(__hadd2(ax3, ay3), az3));
    }

    const __half2 am = __hmin2(__hmin2(am0, am1), __hmin2(am2, am3));
    const float dmin = fminf(__low2float(am), __high2float(am));

    g_dmin[(size_t)(pair * NPTS + q) * SPLITS + sp] = dmin;

    // ---- ticketed tail: last FINB blocks finalize (proven structure) ----
    __syncthreads();
    if (tid == 0) {
        __threadfence();
        s_ticket = atomicAdd(&g_ticket1, 1u);
    }
    __syncthreads();
    const unsigned int t = s_ticket;
    if (t < (unsigned)(nblocks - FINB)) return;

    const int rank = (int)t - (nblocks - FINB);

    if (tid == 0) {
        while (*((volatile unsigned int*)&g_ticket1) < (unsigned)nblocks) { }
    }
    __syncthreads();
    __threadfence();

    const float alpha = *alpha_p;
    const float beta  = *beta_p;
    const float delta = __powf(alpha, -1.0f / beta);

    const int per_blk = nq / FINB;               // 4096 queries
    const int qbase   = rank * per_blk;
    const float4* dm4 = (const float4*)g_dmin;   // 1 float4 per query (SPLITS=4)

    float acc = 0.0f;
    #pragma unroll 4
    for (int i = tid; i < per_blk; i += THREADS) {
        const float4 d = dm4[(size_t)(qbase + i)];
        const float dmn = fminf(fminf(d.x, d.y), fminf(d.z, d.w));
        const float sv = alpha * __powf(dmn, beta) + delta;
        acc += -sv * __expf(-sv);
    }

    #pragma unroll
    for (int o = 16; o > 0; o >>= 1)
        acc += __shfl_down_sync(0xffffffffu, acc, o);
    if ((tid & 31) == 0) red[tid >> 5] = acc;
    __syncthreads();

    if (tid == 0) {
        float v = 0.0f;
        #pragma unroll
        for (int w = 0; w < THREADS / 32; w++) v += red[w];
        g_fpart[rank] = v;
        __threadfence();
        const unsigned int t2 = atomicAdd(&g_ticket2, 1u);
        if (t2 == FINB - 1) {
            float total = 0.0f;
            #pragma unroll
            for (int r = 0; r < FINB; r++)
                total += *((volatile float*)&g_fpart[r]);
            out[0] = total * scale;
            g_ticket1 = 0;       // self-clean for graph replay
            g_ticket2 = 0;
        }
    }
}

extern "C" void kernel_launch(void* const* d_in, const int* in_sizes, int n_in,
                              void* d_out, int out_size)
{
    const float* a1    = (const float*)d_in[0];
    const float* a2    = (const float*)d_in[1];
    const float* alpha = (const float*)d_in[2];
    const float* beta  = (const float*)d_in[3];
    float* out = (float*)d_out;

    const int B  = in_sizes[0] / (NPTS * DIMS);
    const int nq = 2 * B * NPTS;
    const int nblocks = 2 * B * 16 * SPLITS;     // 512 at B=4 — single wave
    const float scale = 50.0f / (float)B;

    gps_kernel<<<nblocks, THREADS>>>(a1, a2, alpha, beta, out, nq, nblocks, scale);
}

// round 14
// speedup vs baseline: 2.0370x; 1.1284x over previous
#include <cuda_runtime.h>
#include <cuda_fp16.h>
#include <math.h>
#include <stdint.h>

// PointLoss_like_GPS — GB300 sm_103a, Round 14
// R11 fp16x2 engine + 2 queries/thread (8 indep accum chains fill fma-pipe
// bubbles), SPLITS=16, FINB=32 wide finalize tail.

#define NPTS    4096
#define DIMS    3
#define THREADS 256
#define SPLITS  16
#define RSPLIT  (NPTS / SPLITS)      // 256 refs per block
#define QPT     2                    // queries per thread
#define QPB     (THREADS * QPT)      // 512 queries per block
#define MAXQ    32768
#define FINB    32

__device__ float        g_dmin[MAXQ * SPLITS];  // [q][split]
__device__ float        g_fpart[FINB];
__device__ unsigned int g_ticket1;
__device__ unsigned int g_ticket2;

__device__ __forceinline__ __half2 h2_of(unsigned int u)
{
    return *reinterpret_cast<const __half2*>(&u);
}

__global__ void __launch_bounds__(THREADS, 4)
gps_kernel(const float* __restrict__ a1,
           const float* __restrict__ a2,
           const float* __restrict__ alpha_p,
           const float* __restrict__ beta_p,
           float* __restrict__ out,
           int nq, int nblocks, float scale)
{
    __shared__ __align__(16) __half2 shX[RSPLIT / 2];   // 128 half2
    __shared__ __align__(16) __half2 shY[RSPLIT / 2];
    __shared__ __align__(16) __half2 shZ[RSPLIT / 2];
    __shared__ float red[THREADS / 32];
    __shared__ unsigned int s_ticket;

    const int tid = threadIdx.x;
    const int bx  = blockIdx.x;

    // bx = pair*(8*SPLITS) + qc*SPLITS + sp   (8 query-chunks of 512)
    const int sp   = bx & (SPLITS - 1);
    const int qc   = (bx >> 4) & 7;
    const int pair = bx >> 7;
    const int b    = pair >> 1;

    const int qA = qc * QPB + tid;             // query 1
    const int qB = qA + THREADS;               // query 2

    const float* base1 = a1 + (size_t)b * NPTS * DIMS;
    const float* base2 = a2 + (size_t)b * NPTS * DIMS;
    const float* samples = (pair & 1) ? base1 : base2;
    const float* refs    = ((pair & 1) ? base2 : base1) + (size_t)sp * RSPLIT * DIMS;

    const float qAx = samples[qA * 3 + 0];
    const float qAy = samples[qA * 3 + 1];
    const float qAz = samples[qA * 3 + 2];
    const float qBx = samples[qB * 3 + 0];
    const float qBy = samples[qB * 3 + 1];
    const float qBz = samples[qB * 3 + 2];

    const __half2 ax2 = __floats2half2_rn(qAx, qAx);
    const __half2 ay2 = __floats2half2_rn(qAy, qAy);
    const __half2 az2 = __floats2half2_rn(qAz, qAz);
    const __half2 bx2 = __floats2half2_rn(qBx, qBx);
    const __half2 by2 = __floats2half2_rn(qBy, qBy);
    const __half2 bz2 = __floats2half2_rn(qBz, qBz);

    // tile: threads [0,128) convert 2 ref points each (AoS fp32 -> half2 SoA)
    if (tid < RSPLIT / 2) {
        const float* p = refs + (size_t)tid * 6;
        shX[tid] = __floats2half2_rn(p[0], p[3]);
        shY[tid] = __floats2half2_rn(p[1], p[4]);
        shZ[tid] = __floats2half2_rn(p[2], p[5]);
    }
    __syncthreads();

    const __half2 HMAXV = __float2half2_rn(65504.0f);
    __half2 am0 = HMAXV, am1 = HMAXV, am2 = HMAXV, am3 = HMAXV;
    __half2 bm0 = HMAXV, bm1 = HMAXV, bm2 = HMAXV, bm3 = HMAXV;

    const uint4* X = (const uint4*)shX;   // 32 groups x 8 pts
    const uint4* Y = (const uint4*)shY;
    const uint4* Z = (const uint4*)shZ;

    #pragma unroll 4
    for (int j = 0; j < RSPLIT / 8; j++) {
        const uint4 xv = X[j], yv = Y[j], zv = Z[j];

        // query A
        {
            const __half2 dx0 = __habs2(__hsub2(ax2, h2_of(xv.x)));
            const __half2 dy0 = __habs2(__hsub2(ay2, h2_of(yv.x)));
            const __half2 dz0 = __habs2(__hsub2(az2, h2_of(zv.x)));
            am0 = __hmin2(am0, __hadd2(__hadd2(dx0, dy0), dz0));

            const __half2 dx1 = __habs2(__hsub2(ax2, h2_of(xv.y)));
            const __half2 dy1 = __habs2(__hsub2(ay2, h2_of(yv.y)));
            const __half2 dz1 = __habs2(__hsub2(az2, h2_of(zv.y)));
            am1 = __hmin2(am1, __hadd2(__hadd2(dx1, dy1), dz1));

            const __half2 dx2 = __habs2(__hsub2(ax2, h2_of(xv.z)));
            const __half2 dy2 = __habs2(__hsub2(ay2, h2_of(yv.z)));
            const __half2 dz2 = __habs2(__hsub2(az2, h2_of(zv.z)));
            am2 = __hmin2(am2, __hadd2(__hadd2(dx2, dy2), dz2));

            const __half2 dx3 = __habs2(__hsub2(ax2, h2_of(xv.w)));
            const __half2 dy3 = __habs2(__hsub2(ay2, h2_of(yv.w)));
            const __half2 dz3 = __habs2(__hsub2(az2, h2_of(zv.w)));
            am3 = __hmin2(am3, __hadd2(__hadd2(dx3, dy3), dz3));
        }
        // query B (independent chains — fills fma bubbles)
        {
            const __half2 dx0 = __habs2(__hsub2(bx2, h2_of(xv.x)));
            const __half2 dy0 = __habs2(__hsub2(by2, h2_of(yv.x)));
            const __half2 dz0 = __habs2(__hsub2(bz2, h2_of(zv.x)));
            bm0 = __hmin2(bm0, __hadd2(__hadd2(dx0, dy0), dz0));

            const __half2 dx1 = __habs2(__hsub2(bx2, h2_of(xv.y)));
            const __half2 dy1 = __habs2(__hsub2(by2, h2_of(yv.y)));
            const __half2 dz1 = __habs2(__hsub2(bz2, h2_of(zv.y)));
            bm1 = __hmin2(bm1, __hadd2(__hadd2(dx1, dy1), dz1));

            const __half2 dx2 = __habs2(__hsub2(bx2, h2_of(xv.z)));
            const __half2 dy2 = __habs2(__hsub2(by2, h2_of(yv.z)));
            const __half2 dz2 = __habs2(__hsub2(bz2, h2_of(zv.z)));
            bm2 = __hmin2(bm2, __hadd2(__hadd2(dx2, dy2), dz2));

            const __half2 dx3 = __habs2(__hsub2(bx2, h2_of(xv.w)));
            const __half2 dy3 = __habs2(__hsub2(by2, h2_of(yv.w)));
            const __half2 dz3 = __habs2(__hsub2(bz2, h2_of(zv.w)));
            bm3 = __hmin2(bm3, __hadd2(__hadd2(dx3, dy3), dz3));
        }
    }

    const __half2 amv = __hmin2(__hmin2(am0, am1), __hmin2(am2, am3));
    const __half2 bmv = __hmin2(__hmin2(bm0, bm1), __hmin2(bm2, bm3));
    const float dminA = fminf(__low2float(amv), __high2float(amv));
    const float dminB = fminf(__low2float(bmv), __high2float(bmv));

    const size_t qrow = (size_t)(pair * NPTS);
    g_dmin[(qrow + qA) * SPLITS + sp] = dminA;
    g_dmin[(qrow + qB) * SPLITS + sp] = dminB;

    // ---- ticketed tail: last FINB blocks finalize ----
    __syncthreads();
    if (tid == 0) {
        __threadfence();
        s_ticket = atomicAdd(&g_ticket1, 1u);
    }
    __syncthreads();
    const unsigned int t = s_ticket;
    if (t < (unsigned)(nblocks - FINB)) return;

    const int rank = (int)t - (nblocks - FINB);

    if (tid == 0) {
        while (*((volatile unsigned int*)&g_ticket1) < (unsigned)nblocks) { }
    }
    __syncthreads();
    __threadfence();

    const float alpha = *alpha_p;
    const float beta  = *beta_p;
    const float delta = __powf(alpha, -1.0f / beta);

    const int per_blk = nq / FINB;               // 1024 queries
    const int qbase   = rank * per_blk;
    const float4* dm4 = (const float4*)g_dmin;   // 4 float4 per query

    float acc = 0.0f;
    #pragma unroll 2
    for (int i = tid; i < per_blk; i += THREADS) {
        const size_t base = (size_t)(qbase + i) * 4;
        const float4 d0 = dm4[base + 0];
        const float4 d1 = dm4[base + 1];
        const float4 d2 = dm4[base + 2];
        const float4 d3 = dm4[base + 3];
        const float m0 = fminf(fminf(d0.x, d0.y), fminf(d0.z, d0.w));
        const float m1 = fminf(fminf(d1.x, d1.y), fminf(d1.z, d1.w));
        const float m2 = fminf(fminf(d2.x, d2.y), fminf(d2.z, d2.w));
        const float m3 = fminf(fminf(d3.x, d3.y), fminf(d3.z, d3.w));
        const float dmn = fminf(fminf(m0, m1), fminf(m2, m3));
        const float sv = alpha * __powf(dmn, beta) + delta;
        acc += -sv * __expf(-sv);
    }

    #pragma unroll
    for (int o = 16; o > 0; o >>= 1)
        acc += __shfl_down_sync(0xffffffffu, acc, o);
    if ((tid & 31) == 0) red[tid >> 5] = acc;
    __syncthreads();

    if (tid == 0) {
        float v = 0.0f;
        #pragma unroll
        for (int w = 0; w < THREADS / 32; w++) v += red[w];
        g_fpart[rank] = v;
        __threadfence();
        const unsigned int t2 = atomicAdd(&g_ticket2, 1u);
        if (t2 == FINB - 1) {
            float total = 0.0f;
            #pragma unroll
            for (int r = 0; r < FINB; r++)
                total += *((volatile float*)&g_fpart[r]);
            out[0] = total * scale;
            g_ticket1 = 0;       // self-clean for graph replay
            g_ticket2 = 0;
        }
    }
}

extern "C" void kernel_launch(void* const* d_in, const int* in_sizes, int n_in,
                              void* d_out, int out_size)
{
    const float* a1    = (const float*)d_in[0];
    const float* a2    = (const float*)d_in[1];
    const float* alpha = (const float*)d_in[2];
    const float* beta  = (const float*)d_in[3];
    float* out = (float*)d_out;

    const int B  = in_sizes[0] / (NPTS * DIMS);
    const int nq = 2 * B * NPTS;
    const int nblocks = 2 * B * 8 * SPLITS;      // 1024 at B=4
    const float scale = 50.0f / (float)B;

    gps_kernel<<<nblocks, THREADS>>>(a1, a2, alpha, beta, out, nq, nblocks, scale);
}